// round 10
// baseline (speedup 1.0000x reference)
#include <cuda_runtime.h>
#include <math.h>

#define B_ 8
#define N_ 256
#define D_ 128

// Scratch (device globals — no allocation allowed in kernel_launch)
__device__ float g_h[B_*N_*D_];     // h = nf@Wn + bn            [b][i][d]
__device__ float g_base[B_*N_*D_];  // a_i + be1                 [b][i][d]
__device__ float g_ajT[B_*D_*N_];   // a_j d-pair major          [b][d/2][j][2]
__device__ unsigned g_cnt  = 0;     // precompute-done counter (self-resetting)
__device__ unsigned g_done = 0;     // block-exit counter       (self-resetting)

// ---- packed f32x2 helpers ----
__device__ __forceinline__ unsigned long long pack2(float lo, float hi) {
    unsigned long long r;
    asm("mov.b64 %0,{%1,%2};" : "=l"(r) : "f"(lo), "f"(hi));
    return r;
}
__device__ __forceinline__ void unpack2(unsigned long long p, float& lo, float& hi) {
    asm("mov.b64 {%0,%1},%2;" : "=f"(lo), "=f"(hi) : "l"(p));
}
#define FMA2(d,a,b,c) asm("fma.rn.f32x2 %0,%1,%2,%3;" : "=l"(d) : "l"(a), "l"(b), "l"(c))
#define ADD2(d,a,b)   asm("add.rn.f32x2 %0,%1,%2;"    : "=l"(d) : "l"(a), "l"(b))

// ---------------------------------------------------------------------------
// ONE kernel. Grid = 512 blocks x 256 threads, __launch_bounds__(256,4)
// => regs <= 64, 4 CTAs/SM, 592 slots >= 512 blocks: whole grid co-resident
// => device-side spin barrier is deadlock-free.
//
// Blocks 0..255: R4 precompute (8-row tile, 3 fused GEMVs) -> signal g_cnt.
// All blocks:    stage weights + rel/adj (independent of precompute),
//                spin until g_cnt == 256, then fused phases (R4 verbatim).
// Last block to finish resets the counters for the next graph replay.
// ---------------------------------------------------------------------------
__global__ void __launch_bounds__(256, 4) mono_kernel(
    const float* __restrict__ nf,
    const int*   __restrict__ adj,
    const float* __restrict__ rel,
    const float* __restrict__ Wn,
    const float* __restrict__ bn,
    const float* __restrict__ We1,
    const float* __restrict__ be1,
    const float* __restrict__ We2,
    const float* __restrict__ Wa,
    const float* __restrict__ ba,
    const float* __restrict__ gamma,
    const float* __restrict__ beta,
    float* __restrict__ out)
{
    __shared__ float      s_nf[8*128];   // precompute input stage (writers only)
    __shared__ float      s_sc[4*256];   // scores -> softmax w; later reused as x
    __shared__ ulonglong2 s_w[128];      // per dp: {wxP,wyP},{wzP,weP}
    __shared__ ulonglong2 s_bt[128];     // per dp: {bsP_i0..i3}
    __shared__ float      s_msg[4*128];  // messages

    const int t   = threadIdx.x;
    const int bid = blockIdx.x;

    // ================= precompute (writer blocks 0..255) =================
    if (bid < 256) {
        const int pb  = bid >> 5;
        const int pi0 = (bid & 31) << 3;

        const float* nfrow = nf + (pb*N_ + pi0)*D_;
        for (int idx = t; idx < 8*128; idx += 256)
            s_nf[idx] = nfrow[idx];
        __syncthreads();

        const int dp = t & 63;
        const int rg = t >> 6;          // 0..3 -> rows rg*2, rg*2+1
        const int r0 = rg*2, r1 = rg*2 + 1;

        unsigned long long hP0 = 0ull, hP1 = 0ull;
        unsigned long long aP0 = 0ull, aP1 = 0ull;
        unsigned long long jP0 = 0ull, jP1 = 0ull;

        #pragma unroll 4
        for (int k = 0; k < 128; k++) {
            unsigned long long wn = *(const unsigned long long*)&Wn [ k       *128 + 2*dp];
            unsigned long long wa = *(const unsigned long long*)&We1[ k       *128 + 2*dp];
            unsigned long long wb = *(const unsigned long long*)&We1[(128 + k)*128 + 2*dp];
            unsigned long long x0 = pack2(s_nf[r0*128 + k], s_nf[r0*128 + k]);
            unsigned long long x1 = pack2(s_nf[r1*128 + k], s_nf[r1*128 + k]);
            FMA2(hP0, x0, wn, hP0);  FMA2(hP1, x1, wn, hP1);
            FMA2(aP0, x0, wa, aP0);  FMA2(aP1, x1, wa, aP1);
            FMA2(jP0, x0, wb, jP0);  FMA2(jP1, x1, wb, jP1);
        }

        unsigned long long bnP = *(const unsigned long long*)&bn [2*dp];
        unsigned long long beP = *(const unsigned long long*)&be1[2*dp];
        ADD2(hP0, hP0, bnP);  ADD2(hP1, hP1, bnP);
        ADD2(aP0, aP0, beP);  ADD2(aP1, aP1, beP);

        unsigned long long* ghp = (unsigned long long*)g_h;
        unsigned long long* gbp = (unsigned long long*)g_base;
        unsigned long long* gjp = (unsigned long long*)g_ajT;
        ghp[(pb*N_ + pi0 + r0)*64 + dp] = hP0;
        ghp[(pb*N_ + pi0 + r1)*64 + dp] = hP1;
        gbp[(pb*N_ + pi0 + r0)*64 + dp] = aP0;
        gbp[(pb*N_ + pi0 + r1)*64 + dp] = aP1;
        gjp[(pb*64 + dp)*256 + pi0 + r0] = jP0;
        gjp[(pb*64 + dp)*256 + pi0 + r1] = jP1;

        __threadfence();               // own stores visible before signal
        __syncthreads();               // all threads fenced
        if (t == 0) atomicAdd(&g_cnt, 1u);
    }

    // ================= fused part (all 512 blocks) =================
    const int b  = bid >> 6;
    const int i0 = (bid & 63) << 2;

    // ---- pre-spin: stage rel-weight columns (input-only) ----
    {
        float* s_wf = (float*)s_w;
        #pragma unroll
        for (int idx = t; idx < 512; idx += 256) {
            int dp = idx >> 3, c = idx & 7;
            int col = 2*dp + (c & 1), w = c >> 1;
            s_wf[idx] = (w < 3) ? We1[(256 + w)*128 + col] : We2[col];
        }
    }

    // ---- pre-spin: load rel/adj, compute rdv + mask (input-only) ----
    const int j = t;
    unsigned long long rxP[4], ryP[4], rdP[4];
    unsigned mbits = 0u;
    #pragma unroll
    for (int i = 0; i < 4; i++) {
        float2 r = *(const float2*)(rel + (size_t)(((b*N_) + (i0 + i))*N_ + j)*2);
        float rdv = sqrtf(r.x*r.x + r.y*r.y);
        rxP[i] = pack2(r.x, r.x);
        ryP[i] = pack2(r.y, r.y);
        rdP[i] = pack2(rdv, rdv);
        if (adj[((b*N_) + (i0 + i))*N_ + j] != 0) mbits |= (1u << i);
    }

    // ---- grid barrier: wait for all 256 precompute tiles ----
    if (t == 0) {
        while (atomicAdd(&g_cnt, 0u) < 256u) { __nanosleep(64); }
        __threadfence();
    }
    __syncthreads();

    // ---- stage packed base tile (depends on g_base) ----
    {
        float* s_btf = (float*)s_bt;
        const float* gb = g_base + (b*N_ + i0)*D_;
        #pragma unroll
        for (int idx = t; idx < 512; idx += 256) {
            int i = idx >> 7, d = idx & 127;
            s_btf[(d >> 1)*8 + i*2 + (d & 1)] = gb[i*D_ + d];
        }
    }
    __syncthreads();

    // ---- phase 1: edge scores, packed f32x2, 8-deep LDG batching ----
    {
        unsigned long long sP[4] = {0ull, 0ull, 0ull, 0ull};

        const unsigned long long* ajp =
            ((const unsigned long long*)g_ajT) + ((size_t)b*64*256 + j);

        #pragma unroll 1
        for (int dp0 = 0; dp0 < 64; dp0 += 8) {
            unsigned long long a8[8];
            #pragma unroll
            for (int u = 0; u < 8; u++) a8[u] = ajp[(dp0 + u)*256];   // 8 LDG.64 in flight

            #pragma unroll
            for (int u = 0; u < 8; u++) {
                const int dp = dp0 + u;
                ulonglong2 wA  = s_w [2*dp];            // {wxP, wyP}  (broadcast)
                ulonglong2 wB  = s_w [2*dp + 1];        // {wzP, weP}
                ulonglong2 b01 = s_bt[2*dp];            // {bsP_i0, bsP_i1}
                ulonglong2 b23 = s_bt[2*dp + 1];        // {bsP_i2, bsP_i3}

                #pragma unroll
                for (int i = 0; i < 4; i++) {
                    unsigned long long bsP = (i == 0) ? b01.x : (i == 1) ? b01.y
                                           : (i == 2) ? b23.x : b23.y;
                    unsigned long long v;
                    ADD2(v, bsP, a8[u]);
                    FMA2(v, rxP[i], wA.x, v);
                    FMA2(v, ryP[i], wA.y, v);
                    FMA2(v, rdP[i], wB.x, v);
                    float lo, hi;
                    unpack2(v, lo, hi);
                    lo = fmaxf(lo, 0.f); hi = fmaxf(hi, 0.f);
                    unsigned long long vr = pack2(lo, hi);
                    FMA2(sP[i], vr, wB.y, sP[i]);
                }
            }
        }

        #pragma unroll
        for (int i = 0; i < 4; i++) {
            float lo, hi;
            unpack2(sP[i], lo, hi);
            float s = lo + hi;
            s_sc[i*256 + j] = ((mbits >> i) & 1u) ? s : -1e30f;
        }
        // be2 omitted — softmax is shift-invariant.
    }
    __syncthreads();

    // ---- phase 2: masked softmax over j (warps 0-3, one row each) ----
    {
        const int w = t >> 5, lane = t & 31;
        if (w < 4) {
            float v[8]; float m = -3.0e38f;
            #pragma unroll
            for (int k = 0; k < 8; k++) { v[k] = s_sc[w*256 + lane + 32*k]; m = fmaxf(m, v[k]); }
            #pragma unroll
            for (int o = 16; o > 0; o >>= 1) m = fmaxf(m, __shfl_xor_sync(0xffffffffu, m, o));
            float sum = 0.f;
            #pragma unroll
            for (int k = 0; k < 8; k++) { v[k] = __expf(v[k] - m); sum += v[k]; }
            #pragma unroll
            for (int o = 16; o > 0; o >>= 1) sum += __shfl_xor_sync(0xffffffffu, sum, o);
            float inv = 1.0f / sum;
            #pragma unroll
            for (int k = 0; k < 8; k++) s_sc[w*256 + lane + 32*k] = v[k] * inv;
        }
    }
    __syncthreads();

    // ---- phase 3: messages[i][d] = sum_j w[i][j] * h[j][d], 8-deep LDG ----
    {
        const int d = t & 127, g = t >> 7;      // g in {0,1} -> rows g*2, g*2+1
        float m0 = 0.f, m1 = 0.f;
        const float* hp = g_h + (size_t)b*N_*D_ + d;
        const float* w0 = s_sc + (g*2    )*256;
        const float* w1 = s_sc + (g*2 + 1)*256;
        #pragma unroll 1
        for (int j0 = 0; j0 < 256; j0 += 8) {
            float hv[8];
            #pragma unroll
            for (int u = 0; u < 8; u++) hv[u] = hp[(j0 + u)*D_];    // 8 LDG.32 in flight
            const float4 wa0 = *(const float4*)(w0 + j0);
            const float4 wa1 = *(const float4*)(w0 + j0 + 4);
            const float4 wb0 = *(const float4*)(w1 + j0);
            const float4 wb1 = *(const float4*)(w1 + j0 + 4);
            m0 = fmaf(wa0.x, hv[0], m0); m1 = fmaf(wb0.x, hv[0], m1);
            m0 = fmaf(wa0.y, hv[1], m0); m1 = fmaf(wb0.y, hv[1], m1);
            m0 = fmaf(wa0.z, hv[2], m0); m1 = fmaf(wb0.z, hv[2], m1);
            m0 = fmaf(wa0.w, hv[3], m0); m1 = fmaf(wb0.w, hv[3], m1);
            m0 = fmaf(wa1.x, hv[4], m0); m1 = fmaf(wb1.x, hv[4], m1);
            m0 = fmaf(wa1.y, hv[5], m0); m1 = fmaf(wb1.y, hv[5], m1);
            m0 = fmaf(wa1.z, hv[6], m0); m1 = fmaf(wb1.z, hv[6], m1);
            m0 = fmaf(wa1.w, hv[7], m0); m1 = fmaf(wb1.w, hv[7], m1);
        }
        s_msg[(g*2    )*128 + d] = m0;
        s_msg[(g*2 + 1)*128 + d] = m1;
    }
    __syncthreads();

    // ---- phase 4: aggregated = relu(msg @ Wa + ba); x = nf + agg, 8-deep ----
    {
        const int dq = t & 127, g = t >> 7;
        float a0 = 0.f, a1 = 0.f;
        const float* m0p = s_msg + (g*2    )*128;
        const float* m1p = s_msg + (g*2 + 1)*128;
        #pragma unroll 1
        for (int d0 = 0; d0 < 128; d0 += 8) {
            float wv[8];
            #pragma unroll
            for (int u = 0; u < 8; u++) wv[u] = Wa[(d0 + u)*128 + dq];  // 8 LDG.32 in flight
            #pragma unroll
            for (int u = 0; u < 8; u++) {
                a0 = fmaf(m0p[d0 + u], wv[u], a0);
                a1 = fmaf(m1p[d0 + u], wv[u], a1);
            }
        }
        const float bav = ba[dq];
        float* s_x = s_sc;   // scores dead after phase 3; reuse as x
        int r0 = g*2, r1 = g*2 + 1;
        s_x[r0*128 + dq] = nf[(b*N_ + i0 + r0)*D_ + dq] + fmaxf(a0 + bav, 0.f);
        s_x[r1*128 + dq] = nf[(b*N_ + i0 + r1)*D_ + dq] + fmaxf(a1 + bav, 0.f);
    }
    __syncthreads();

    // ---- phase 5: layernorm over d, write output (warps 0-3, one row each) ----
    {
        const int w = t >> 5, lane = t & 31;
        if (w < 4) {
            const float* s_x = s_sc;
            float4 xv = *(const float4*)(s_x + w*128 + lane*4);
            float sm = xv.x + xv.y + xv.z + xv.w;
            float sq = fmaf(xv.x, xv.x, fmaf(xv.y, xv.y, fmaf(xv.z, xv.z, xv.w*xv.w)));
            #pragma unroll
            for (int o = 16; o > 0; o >>= 1) {
                sm += __shfl_xor_sync(0xffffffffu, sm, o);
                sq += __shfl_xor_sync(0xffffffffu, sq, o);
            }
            float mu   = sm * (1.0f/128.0f);
            float var  = fmaf(sq, 1.0f/128.0f, -mu*mu);
            float rstd = rsqrtf(var + 1e-5f);
            float4 gv = *(const float4*)(gamma + lane*4);
            float4 bv = *(const float4*)(beta  + lane*4);
            float4 o4;
            o4.x = fmaf((xv.x - mu)*rstd, gv.x, bv.x);
            o4.y = fmaf((xv.y - mu)*rstd, gv.y, bv.y);
            o4.z = fmaf((xv.z - mu)*rstd, gv.z, bv.z);
            o4.w = fmaf((xv.w - mu)*rstd, gv.w, bv.w);
            *(float4*)(out + (size_t)(b*N_ + i0 + w)*D_ + lane*4) = o4;
        }
    }

    // ---- counter reset: last block out restores zeros for next replay ----
    __syncthreads();
    if (t == 0) {
        unsigned old = atomicAdd(&g_done, 1u);
        if (old == 511u) {
            g_cnt  = 0u;
            __threadfence();
            g_done = 0u;
            __threadfence();
        }
    }
}

extern "C" void kernel_launch(void* const* d_in, const int* in_sizes, int n_in,
                              void* d_out, int out_size)
{
    const float* nf    = (const float*)d_in[0];
    const int*   adj   = (const int*)  d_in[1];
    const float* rel   = (const float*)d_in[2];
    const float* Wn    = (const float*)d_in[3];
    const float* bn    = (const float*)d_in[4];
    const float* We1   = (const float*)d_in[5];
    const float* be1   = (const float*)d_in[6];
    const float* We2   = (const float*)d_in[7];
    // d_in[8] = be2: unused (softmax shift-invariance makes it a no-op)
    const float* Wa    = (const float*)d_in[9];
    const float* ba    = (const float*)d_in[10];
    const float* gamma = (const float*)d_in[11];
    const float* beta  = (const float*)d_in[12];
    float* out = (float*)d_out;

    mono_kernel<<<512, 256>>>(nf, adj, rel, Wn, bn, We1, be1, We2,
                              Wa, ba, gamma, beta, out);
}

// round 11
// speedup vs baseline: 1.1715x; 1.1715x over previous
#include <cuda_runtime.h>
#include <math.h>

#define B_ 8
#define N_ 256
#define D_ 128

// Scratch (device globals — no allocation allowed in kernel_launch)
__device__ float g_h[B_*N_*D_];     // h = nf@Wn + bn            [b][i][d]
__device__ float g_base[B_*N_*D_];  // a_i + be1                 [b][i][d]
__device__ float g_ajT[B_*D_*N_];   // a_j d-pair major          [b][d/2][j][2]

// ---- packed f32x2 helpers ----
__device__ __forceinline__ unsigned long long pack2(float lo, float hi) {
    unsigned long long r;
    asm("mov.b64 %0,{%1,%2};" : "=l"(r) : "f"(lo), "f"(hi));
    return r;
}
__device__ __forceinline__ void unpack2(unsigned long long p, float& lo, float& hi) {
    asm("mov.b64 {%0,%1},%2;" : "=f"(lo), "=f"(hi) : "l"(p));
}
#define FMA2(d,a,b,c) asm("fma.rn.f32x2 %0,%1,%2,%3;" : "=l"(d) : "l"(a), "l"(b), "l"(c))
#define ADD2(d,a,b)   asm("add.rn.f32x2 %0,%1,%2;"    : "=l"(d) : "l"(a), "l"(b))

// ---------------------------------------------------------------------------
// Kernel 1: R4-exact precompute (8-row tiles, 256 blocks, 3 fused GEMVs).
// Triggers programmatic launch of the fused kernel at entry so the fused
// prologue overlaps this kernel's execution.
// ---------------------------------------------------------------------------
__global__ void __launch_bounds__(256, 4) precompute_kernel(
    const float* __restrict__ nf,
    const float* __restrict__ Wn,  const float* __restrict__ bn,
    const float* __restrict__ We1, const float* __restrict__ be1)
{
    cudaTriggerProgrammaticLaunchCompletion();

    __shared__ float s_nf[8*128];
    const int t  = threadIdx.x;
    const int b  = blockIdx.x >> 5;
    const int i0 = (blockIdx.x & 31) << 3;

    const float* nfrow = nf + (b*N_ + i0)*D_;
    for (int idx = t; idx < 8*128; idx += 256)
        s_nf[idx] = nfrow[idx];
    __syncthreads();

    const int dp = t & 63;
    const int rg = t >> 6;          // 0..3 -> rows rg*2, rg*2+1
    const int r0 = rg*2, r1 = rg*2 + 1;

    unsigned long long hP0 = 0ull, hP1 = 0ull;
    unsigned long long aP0 = 0ull, aP1 = 0ull;
    unsigned long long jP0 = 0ull, jP1 = 0ull;

    #pragma unroll 4
    for (int k = 0; k < 128; k++) {
        unsigned long long wn = *(const unsigned long long*)&Wn [ k       *128 + 2*dp];
        unsigned long long wa = *(const unsigned long long*)&We1[ k       *128 + 2*dp];
        unsigned long long wb = *(const unsigned long long*)&We1[(128 + k)*128 + 2*dp];
        unsigned long long x0 = pack2(s_nf[r0*128 + k], s_nf[r0*128 + k]);
        unsigned long long x1 = pack2(s_nf[r1*128 + k], s_nf[r1*128 + k]);
        FMA2(hP0, x0, wn, hP0);  FMA2(hP1, x1, wn, hP1);
        FMA2(aP0, x0, wa, aP0);  FMA2(aP1, x1, wa, aP1);
        FMA2(jP0, x0, wb, jP0);  FMA2(jP1, x1, wb, jP1);
    }

    unsigned long long bnP = *(const unsigned long long*)&bn [2*dp];
    unsigned long long beP = *(const unsigned long long*)&be1[2*dp];
    ADD2(hP0, hP0, bnP);  ADD2(hP1, hP1, bnP);
    ADD2(aP0, aP0, beP);  ADD2(aP1, aP1, beP);

    unsigned long long* ghp = (unsigned long long*)g_h;
    unsigned long long* gbp = (unsigned long long*)g_base;
    unsigned long long* gjp = (unsigned long long*)g_ajT;
    ghp[(b*N_ + i0 + r0)*64 + dp] = hP0;
    ghp[(b*N_ + i0 + r1)*64 + dp] = hP1;
    gbp[(b*N_ + i0 + r0)*64 + dp] = aP0;
    gbp[(b*N_ + i0 + r1)*64 + dp] = aP1;
    gjp[(b*64 + dp)*256 + i0 + r0] = jP0;
    gjp[(b*64 + dp)*256 + i0 + r1] = jP1;
}

// ---------------------------------------------------------------------------
// Kernel 2: fused edge-MLP -> softmax -> messages -> out GEMM -> layernorm.
// Launched with programmatic stream serialization: the prologue (weight
// staging + rel/adj loads) runs concurrently with precompute; the
// cudaGridDependencySynchronize() gates the first use of g_base/g_ajT/g_h.
// Block = (b, 4-row i-tile), 256 threads. Grid = 512 blocks. (R4 body.)
// ---------------------------------------------------------------------------
__global__ void __launch_bounds__(256, 4) fused_kernel(
    const float* __restrict__ nf,
    const int*   __restrict__ adj,
    const float* __restrict__ rel,
    const float* __restrict__ We1,
    const float* __restrict__ We2,
    const float* __restrict__ Wa,
    const float* __restrict__ ba,
    const float* __restrict__ gamma,
    const float* __restrict__ beta,
    float* __restrict__ out)
{
    __shared__ float      s_sc[4*256];   // scores -> softmax w; later reused as x
    __shared__ ulonglong2 s_w[128];      // per dp: {wxP,wyP},{wzP,weP}
    __shared__ ulonglong2 s_bt[128];     // per dp: {bsP_i0..i3}
    __shared__ float      s_msg[4*128];  // messages

    const int t  = threadIdx.x;
    const int b  = blockIdx.x >> 6;
    const int i0 = (blockIdx.x & 63) << 2;

    // ---- pre-sync prologue: stage rel-weight columns (input-only) ----
    {
        float* s_wf = (float*)s_w;
        #pragma unroll
        for (int idx = t; idx < 512; idx += 256) {
            int dp = idx >> 3, c = idx & 7;
            int col = 2*dp + (c & 1), w = c >> 1;
            s_wf[idx] = (w < 3) ? We1[(256 + w)*128 + col] : We2[col];
        }
    }

    // ---- pre-sync prologue: rel/adj loads, rdv + mask (input-only) ----
    const int j = t;
    unsigned long long rxP[4], ryP[4], rdP[4];
    unsigned mbits = 0u;
    #pragma unroll
    for (int i = 0; i < 4; i++) {
        float2 r = *(const float2*)(rel + (size_t)(((b*N_) + (i0 + i))*N_ + j)*2);
        float rdv = sqrtf(r.x*r.x + r.y*r.y);
        rxP[i] = pack2(r.x, r.x);
        ryP[i] = pack2(r.y, r.y);
        rdP[i] = pack2(rdv, rdv);
        if (adj[((b*N_) + (i0 + i))*N_ + j] != 0) mbits |= (1u << i);
    }

    // ---- wait for precompute grid (memory visibility guaranteed) ----
    cudaGridDependencySynchronize();

    // ---- stage packed base tile (depends on g_base) ----
    {
        float* s_btf = (float*)s_bt;
        const float* gb = g_base + (b*N_ + i0)*D_;
        #pragma unroll
        for (int idx = t; idx < 512; idx += 256) {
            int i = idx >> 7, d = idx & 127;
            s_btf[(d >> 1)*8 + i*2 + (d & 1)] = gb[i*D_ + d];
        }
    }
    __syncthreads();

    // ---- phase 1: edge scores, packed f32x2, 8-deep LDG batching ----
    {
        unsigned long long sP[4] = {0ull, 0ull, 0ull, 0ull};

        const unsigned long long* ajp =
            ((const unsigned long long*)g_ajT) + ((size_t)b*64*256 + j);

        #pragma unroll 1
        for (int dp0 = 0; dp0 < 64; dp0 += 8) {
            unsigned long long a8[8];
            #pragma unroll
            for (int u = 0; u < 8; u++) a8[u] = ajp[(dp0 + u)*256];   // 8 LDG.64 in flight

            #pragma unroll
            for (int u = 0; u < 8; u++) {
                const int dp = dp0 + u;
                ulonglong2 wA  = s_w [2*dp];            // {wxP, wyP}  (broadcast)
                ulonglong2 wB  = s_w [2*dp + 1];        // {wzP, weP}
                ulonglong2 b01 = s_bt[2*dp];            // {bsP_i0, bsP_i1}
                ulonglong2 b23 = s_bt[2*dp + 1];        // {bsP_i2, bsP_i3}

                #pragma unroll
                for (int i = 0; i < 4; i++) {
                    unsigned long long bsP = (i == 0) ? b01.x : (i == 1) ? b01.y
                                           : (i == 2) ? b23.x : b23.y;
                    unsigned long long v;
                    ADD2(v, bsP, a8[u]);
                    FMA2(v, rxP[i], wA.x, v);
                    FMA2(v, ryP[i], wA.y, v);
                    FMA2(v, rdP[i], wB.x, v);
                    float lo, hi;
                    unpack2(v, lo, hi);
                    lo = fmaxf(lo, 0.f); hi = fmaxf(hi, 0.f);
                    unsigned long long vr = pack2(lo, hi);
                    FMA2(sP[i], vr, wB.y, sP[i]);
                }
            }
        }

        #pragma unroll
        for (int i = 0; i < 4; i++) {
            float lo, hi;
            unpack2(sP[i], lo, hi);
            float s = lo + hi;
            s_sc[i*256 + j] = ((mbits >> i) & 1u) ? s : -1e30f;
        }
        // be2 omitted — softmax is shift-invariant.
    }
    __syncthreads();

    // ---- phase 2: masked softmax over j (warps 0-3, one row each) ----
    {
        const int w = t >> 5, lane = t & 31;
        if (w < 4) {
            float v[8]; float m = -3.0e38f;
            #pragma unroll
            for (int k = 0; k < 8; k++) { v[k] = s_sc[w*256 + lane + 32*k]; m = fmaxf(m, v[k]); }
            #pragma unroll
            for (int o = 16; o > 0; o >>= 1) m = fmaxf(m, __shfl_xor_sync(0xffffffffu, m, o));
            float sum = 0.f;
            #pragma unroll
            for (int k = 0; k < 8; k++) { v[k] = __expf(v[k] - m); sum += v[k]; }
            #pragma unroll
            for (int o = 16; o > 0; o >>= 1) sum += __shfl_xor_sync(0xffffffffu, sum, o);
            float inv = 1.0f / sum;
            #pragma unroll
            for (int k = 0; k < 8; k++) s_sc[w*256 + lane + 32*k] = v[k] * inv;
        }
    }
    __syncthreads();

    // ---- phase 3: messages[i][d] = sum_j w[i][j] * h[j][d], 8-deep LDG ----
    {
        const int d = t & 127, g = t >> 7;      // g in {0,1} -> rows g*2, g*2+1
        float m0 = 0.f, m1 = 0.f;
        const float* hp = g_h + (size_t)b*N_*D_ + d;
        const float* w0 = s_sc + (g*2    )*256;
        const float* w1 = s_sc + (g*2 + 1)*256;
        #pragma unroll 1
        for (int j0 = 0; j0 < 256; j0 += 8) {
            float hv[8];
            #pragma unroll
            for (int u = 0; u < 8; u++) hv[u] = hp[(j0 + u)*D_];    // 8 LDG.32 in flight
            const float4 wa0 = *(const float4*)(w0 + j0);
            const float4 wa1 = *(const float4*)(w0 + j0 + 4);
            const float4 wb0 = *(const float4*)(w1 + j0);
            const float4 wb1 = *(const float4*)(w1 + j0 + 4);
            m0 = fmaf(wa0.x, hv[0], m0); m1 = fmaf(wb0.x, hv[0], m1);
            m0 = fmaf(wa0.y, hv[1], m0); m1 = fmaf(wb0.y, hv[1], m1);
            m0 = fmaf(wa0.z, hv[2], m0); m1 = fmaf(wb0.z, hv[2], m1);
            m0 = fmaf(wa0.w, hv[3], m0); m1 = fmaf(wb0.w, hv[3], m1);
            m0 = fmaf(wa1.x, hv[4], m0); m1 = fmaf(wb1.x, hv[4], m1);
            m0 = fmaf(wa1.y, hv[5], m0); m1 = fmaf(wb1.y, hv[5], m1);
            m0 = fmaf(wa1.z, hv[6], m0); m1 = fmaf(wb1.z, hv[6], m1);
            m0 = fmaf(wa1.w, hv[7], m0); m1 = fmaf(wb1.w, hv[7], m1);
        }
        s_msg[(g*2    )*128 + d] = m0;
        s_msg[(g*2 + 1)*128 + d] = m1;
    }
    __syncthreads();

    // ---- phase 4: aggregated = relu(msg @ Wa + ba); x = nf + agg, 8-deep ----
    {
        const int dq = t & 127, g = t >> 7;
        float a0 = 0.f, a1 = 0.f;
        const float* m0p = s_msg + (g*2    )*128;
        const float* m1p = s_msg + (g*2 + 1)*128;
        #pragma unroll 1
        for (int d0 = 0; d0 < 128; d0 += 8) {
            float wv[8];
            #pragma unroll
            for (int u = 0; u < 8; u++) wv[u] = Wa[(d0 + u)*128 + dq];  // 8 LDG.32 in flight
            #pragma unroll
            for (int u = 0; u < 8; u++) {
                a0 = fmaf(m0p[d0 + u], wv[u], a0);
                a1 = fmaf(m1p[d0 + u], wv[u], a1);
            }
        }
        const float bav = ba[dq];
        float* s_x = s_sc;   // scores dead after phase 3; reuse as x
        int r0 = g*2, r1 = g*2 + 1;
        s_x[r0*128 + dq] = nf[(b*N_ + i0 + r0)*D_ + dq] + fmaxf(a0 + bav, 0.f);
        s_x[r1*128 + dq] = nf[(b*N_ + i0 + r1)*D_ + dq] + fmaxf(a1 + bav, 0.f);
    }
    __syncthreads();

    // ---- phase 5: layernorm over d, write output (warps 0-3, one row each) ----
    {
        const int w = t >> 5, lane = t & 31;
        if (w < 4) {
            const float* s_x = s_sc;
            float4 xv = *(const float4*)(s_x + w*128 + lane*4);
            float sm = xv.x + xv.y + xv.z + xv.w;
            float sq = fmaf(xv.x, xv.x, fmaf(xv.y, xv.y, fmaf(xv.z, xv.z, xv.w*xv.w)));
            #pragma unroll
            for (int o = 16; o > 0; o >>= 1) {
                sm += __shfl_xor_sync(0xffffffffu, sm, o);
                sq += __shfl_xor_sync(0xffffffffu, sq, o);
            }
            float mu   = sm * (1.0f/128.0f);
            float var  = fmaf(sq, 1.0f/128.0f, -mu*mu);
            float rstd = rsqrtf(var + 1e-5f);
            float4 gv = *(const float4*)(gamma + lane*4);
            float4 bv = *(const float4*)(beta  + lane*4);
            float4 o4;
            o4.x = fmaf((xv.x - mu)*rstd, gv.x, bv.x);
            o4.y = fmaf((xv.y - mu)*rstd, gv.y, bv.y);
            o4.z = fmaf((xv.z - mu)*rstd, gv.z, bv.z);
            o4.w = fmaf((xv.w - mu)*rstd, gv.w, bv.w);
            *(float4*)(out + (size_t)(b*N_ + i0 + w)*D_ + lane*4) = o4;
        }
    }
}

extern "C" void kernel_launch(void* const* d_in, const int* in_sizes, int n_in,
                              void* d_out, int out_size)
{
    const float* nf    = (const float*)d_in[0];
    const int*   adj   = (const int*)  d_in[1];
    const float* rel   = (const float*)d_in[2];
    const float* Wn    = (const float*)d_in[3];
    const float* bn    = (const float*)d_in[4];
    const float* We1   = (const float*)d_in[5];
    const float* be1   = (const float*)d_in[6];
    const float* We2   = (const float*)d_in[7];
    // d_in[8] = be2: unused (softmax shift-invariance makes it a no-op)
    const float* Wa    = (const float*)d_in[9];
    const float* ba    = (const float*)d_in[10];
    const float* gamma = (const float*)d_in[11];
    const float* beta  = (const float*)d_in[12];
    float* out = (float*)d_out;

    precompute_kernel<<<256, 256>>>(nf, Wn, bn, We1, be1);

    // Fused kernel with programmatic dependent launch: its prologue overlaps
    // the precompute kernel; cudaGridDependencySynchronize() gates data use.
    cudaLaunchConfig_t cfg = {};
    cfg.gridDim  = dim3(512, 1, 1);
    cfg.blockDim = dim3(256, 1, 1);
    cudaLaunchAttribute attrs[1];
    attrs[0].id = cudaLaunchAttributeProgrammaticStreamSerialization;
    attrs[0].val.programmaticStreamSerializationAllowed = 1;
    cfg.attrs = attrs;
    cfg.numAttrs = 1;
    cudaLaunchKernelEx(&cfg, fused_kernel,
                       nf, adj, rel, We1, We2, Wa, ba, gamma, beta, out);
}